// round 2
// baseline (speedup 1.0000x reference)
#include <cuda_runtime.h>
#include <cstdint>

#define NN 20000
#define NE 320000
#define ET 340000   /* NE + NN self loops */
#define F1 256
#define HD 512      /* 8 heads * 64 */
#define NC 16
#define NEG 0.2f

/* ----------------------------- device scratch ---------------------------- */
__device__ float g_xl1[NN * HD];
__device__ float g_xr1[NN * HD];
__device__ float g_h  [NN * HD];
__device__ float g_xl2[NN * NC];
__device__ float g_xr2[NN * NC];
__device__ float g_Wt [32 * HD];      /* transposed layer-2 weights [32][512] */
__device__ int   g_deg[NN];
__device__ int   g_rowptr[NN + 1];
__device__ int   g_wp[NN];
__device__ int   g_col[ET];
__device__ int   g_is64;

/* --------------------------- small device helpers ------------------------ */
__device__ __forceinline__ float lrelu(float x) { return x > 0.f ? x : NEG * x; }

__device__ __forceinline__ unsigned long long pk2(float x, float y) {
    unsigned long long r;
    asm("mov.b64 %0, {%1, %2};" : "=l"(r)
        : "r"(__float_as_uint(x)), "r"(__float_as_uint(y)));
    return r;
}
__device__ __forceinline__ void fma2(unsigned long long& c,
                                     unsigned long long a, unsigned long long b) {
    asm("fma.rn.f32x2 %0, %1, %2, %0;" : "+l"(c) : "l"(a), "l"(b));
}
__device__ __forceinline__ float2 upk2(unsigned long long v) {
    unsigned lo, hi;
    asm("mov.b64 {%0, %1}, %2;" : "=r"(lo), "=r"(hi) : "l"(v));
    return make_float2(__uint_as_float(lo), __uint_as_float(hi));
}

__device__ __forceinline__ int edge_val(const void* ei, int idx) {
    if (g_is64) return (int)(((const long long*)ei)[idx]);
    return ((const int*)ei)[idx];
}

/* --------------------------- dtype detection ----------------------------- */
__global__ void k_detect(const int* __restrict__ ei32) {
    __shared__ int s;
    if (threadIdx.x == 0) s = 0;
    __syncthreads();
    int v = ei32[threadIdx.x * 2 + 1];
    if (v != 0) atomicOr(&s, 1);
    __syncthreads();
    if (threadIdx.x == 0) g_is64 = (s == 0) ? 1 : 0;
}

/* ------------------------------- CSR build ------------------------------- */
__global__ void k_zero_deg() {
    int i = blockIdx.x * blockDim.x + threadIdx.x;
    if (i < NN) g_deg[i] = 0;
}

__global__ void k_hist(const void* __restrict__ ei) {
    int i = blockIdx.x * blockDim.x + threadIdx.x;
    if (i >= ET) return;
    int dst = (i < NE) ? edge_val(ei, NE + i) : (i - NE);
    atomicAdd(&g_deg[dst], 1);
}

/* single block, 1024 threads, 20 elems/thread, 2 barriers total */
__global__ void k_scan() {
    __shared__ int wsum[32];
    int tid = threadIdx.x, lane = tid & 31, wid = tid >> 5;
    int base = tid * 20;
    int loc[20];
    int s = 0;
    #pragma unroll
    for (int i = 0; i < 20; i++) {
        int v = (base + i < NN) ? g_deg[base + i] : 0;
        loc[i] = s; s += v;
    }
    int ws = s;
    #pragma unroll
    for (int off = 1; off < 32; off <<= 1) {
        int t = __shfl_up_sync(0xffffffffu, ws, off);
        if (lane >= off) ws += t;
    }
    if (lane == 31) wsum[wid] = ws;
    __syncthreads();
    if (wid == 0) {
        int v = wsum[lane];
        int x = v;
        #pragma unroll
        for (int off = 1; off < 32; off <<= 1) {
            int t = __shfl_up_sync(0xffffffffu, x, off);
            if (lane >= off) x += t;
        }
        wsum[lane] = x - v;   /* exclusive */
    }
    __syncthreads();
    int thr_excl = wsum[wid] + ws - s;
    #pragma unroll
    for (int i = 0; i < 20; i++) {
        int idx = base + i;
        if (idx < NN) {
            int e = thr_excl + loc[i];
            g_rowptr[idx] = e;
            g_wp[idx] = e;
        }
    }
    if (tid == 0) g_rowptr[NN] = ET;
}

__global__ void k_scatter(const void* __restrict__ ei) {
    int i = blockIdx.x * blockDim.x + threadIdx.x;
    if (i >= ET) return;
    int src, dst;
    if (i < NE) { src = edge_val(ei, i); dst = edge_val(ei, NE + i); }
    else        { src = i - NE; dst = i - NE; }
    int pos = atomicAdd(&g_wp[dst], 1);
    g_col[pos] = src;
}

/* -------------------- SGEMM, k-paired fp32x2 FMA ------------------------- */
/* C{0,1}[M,N] = A[M,K] @ W{0,1}[K,N] + b{0,1}; blockIdx.z selects pair.
   Per-thread 8x4 tile; accumulators hold (even-k, odd-k) partial sums. */
#define BM 128
#define BN 64
#define BK 16
#define KH 8   /* BK/2 */

__global__ void __launch_bounds__(256, 2)
k_sgemm2(const float* __restrict__ A, int M, int N, int K,
         const float* __restrict__ W0, const float* __restrict__ b0, float* __restrict__ C0,
         const float* __restrict__ W1, const float* __restrict__ b1, float* __restrict__ C1)
{
    const float* W    = blockIdx.z ? W1 : W0;
    const float* bias = blockIdx.z ? b1 : b0;
    float*       C    = blockIdx.z ? C1 : C0;

    __shared__ __align__(16) unsigned long long As2[2][KH][BM];
    __shared__ __align__(16) unsigned long long Bs2[2][KH][BN];

    int tid = threadIdx.x;
    int bm = blockIdx.x * BM;
    int bn = blockIdx.y * BN;

    /* A-load mapping: row a_r, k-offset a_k (0 or 8), 2 float4 along K */
    int a_r = tid >> 1;
    int a_k = (tid & 1) << 3;
    /* B-load mapping: row-pair rp (0..7), cols bc..bc+1 */
    int rp = tid >> 5;
    int bc = (tid & 31) << 1;
    /* compute mapping */
    int tx = tid & 15, ty = tid >> 4;
    int trow = ty << 3, tcol = tx << 2;

    unsigned long long acc[8][4];
    #pragma unroll
    for (int i = 0; i < 8; i++)
        #pragma unroll
        for (int j = 0; j < 4; j++) acc[i][j] = 0ull;

    const int nt = K / BK;

    /* prologue: load tile 0 */
    {
        int m = bm + a_r;
        float4 qa0 = make_float4(0.f, 0.f, 0.f, 0.f), qa1 = qa0;
        if (m < M) {
            qa0 = *reinterpret_cast<const float4*>(A + (size_t)m * K + a_k);
            qa1 = *reinterpret_cast<const float4*>(A + (size_t)m * K + a_k + 4);
        }
        int kh = a_k >> 1;
        As2[0][kh + 0][a_r] = pk2(qa0.x, qa0.y);
        As2[0][kh + 1][a_r] = pk2(qa0.z, qa0.w);
        As2[0][kh + 2][a_r] = pk2(qa1.x, qa1.y);
        As2[0][kh + 3][a_r] = pk2(qa1.z, qa1.w);
        float2 u = *reinterpret_cast<const float2*>(W + (size_t)(2 * rp) * N + bn + bc);
        float2 v = *reinterpret_cast<const float2*>(W + (size_t)(2 * rp + 1) * N + bn + bc);
        ulonglong2 pb;
        pb.x = pk2(u.x, v.x);
        pb.y = pk2(u.y, v.y);
        *reinterpret_cast<ulonglong2*>(&Bs2[0][rp][bc]) = pb;
    }
    __syncthreads();

    for (int t = 0; t < nt; t++) {
        int cur = t & 1;
        bool pf = (t + 1 < nt);
        float4 qa0 = make_float4(0.f, 0.f, 0.f, 0.f), qa1 = qa0;
        float2 u = make_float2(0.f, 0.f), v = u;
        if (pf) {
            int k0 = (t + 1) * BK;
            int m = bm + a_r;
            if (m < M) {
                qa0 = *reinterpret_cast<const float4*>(A + (size_t)m * K + k0 + a_k);
                qa1 = *reinterpret_cast<const float4*>(A + (size_t)m * K + k0 + a_k + 4);
            }
            u = *reinterpret_cast<const float2*>(W + (size_t)(k0 + 2 * rp) * N + bn + bc);
            v = *reinterpret_cast<const float2*>(W + (size_t)(k0 + 2 * rp + 1) * N + bn + bc);
        }

        #pragma unroll
        for (int k2 = 0; k2 < KH; k2++) {
            ulonglong2 a0 = *reinterpret_cast<const ulonglong2*>(&As2[cur][k2][trow]);
            ulonglong2 a1 = *reinterpret_cast<const ulonglong2*>(&As2[cur][k2][trow + 2]);
            ulonglong2 a2 = *reinterpret_cast<const ulonglong2*>(&As2[cur][k2][trow + 4]);
            ulonglong2 a3 = *reinterpret_cast<const ulonglong2*>(&As2[cur][k2][trow + 6]);
            ulonglong2 bb0 = *reinterpret_cast<const ulonglong2*>(&Bs2[cur][k2][tcol]);
            ulonglong2 bb1 = *reinterpret_cast<const ulonglong2*>(&Bs2[cur][k2][tcol + 2]);
            unsigned long long av[8] = {a0.x, a0.y, a1.x, a1.y, a2.x, a2.y, a3.x, a3.y};
            unsigned long long bv[4] = {bb0.x, bb0.y, bb1.x, bb1.y};
            #pragma unroll
            for (int i = 0; i < 8; i++)
                #pragma unroll
                for (int j = 0; j < 4; j++)
                    fma2(acc[i][j], av[i], bv[j]);
        }

        if (pf) {
            __syncthreads();
            int nxt = cur ^ 1;
            int kh = a_k >> 1;
            As2[nxt][kh + 0][a_r] = pk2(qa0.x, qa0.y);
            As2[nxt][kh + 1][a_r] = pk2(qa0.z, qa0.w);
            As2[nxt][kh + 2][a_r] = pk2(qa1.x, qa1.y);
            As2[nxt][kh + 3][a_r] = pk2(qa1.z, qa1.w);
            ulonglong2 pb;
            pb.x = pk2(u.x, v.x);
            pb.y = pk2(u.y, v.y);
            *reinterpret_cast<ulonglong2*>(&Bs2[nxt][rp][bc]) = pb;
            __syncthreads();
        }
    }

    float4 bias4 = *reinterpret_cast<const float4*>(bias + bn + tcol);
    #pragma unroll
    for (int i = 0; i < 8; i++) {
        int m = bm + trow + i;
        if (m < M) {
            float2 f0 = upk2(acc[i][0]);
            float2 f1 = upk2(acc[i][1]);
            float2 f2 = upk2(acc[i][2]);
            float2 f3 = upk2(acc[i][3]);
            float4 o = make_float4(f0.x + f0.y + bias4.x,
                                   f1.x + f1.y + bias4.y,
                                   f2.x + f2.y + bias4.z,
                                   f3.x + f3.y + bias4.w);
            *reinterpret_cast<float4*>(C + (size_t)m * N + bn + tcol) = o;
        }
    }
}

/* -------------------- layer-1 GATv2 (flash-style softmax) ---------------- */
__global__ void __launch_bounds__(128)
k_gat1(const float* __restrict__ xl, const float* __restrict__ xr,
       const float* __restrict__ att, const float* __restrict__ bias,
       float* __restrict__ hout)
{
    int node = blockIdx.x;
    int tid = threadIdx.x;

    float4 xrv = reinterpret_cast<const float4*>(xr + (size_t)node * HD)[tid];
    float4 av  = reinterpret_cast<const float4*>(att)[tid];
    float4 bv  = reinterpret_cast<const float4*>(bias)[tid];

    int jb = g_rowptr[node], je = g_rowptr[node + 1];

    float m = -1e30f, s = 0.f;
    float4 acc = make_float4(0.f, 0.f, 0.f, 0.f);

    const float4* xlp = reinterpret_cast<const float4*>(xl);
    float4 xlv = make_float4(0.f, 0.f, 0.f, 0.f);
    if (jb < je) {
        int src0 = g_col[jb];
        xlv = xlp[(size_t)src0 * 128 + tid];
    }
    for (int j = jb; j < je; j++) {
        float4 cur = xlv;
        if (j + 1 < je) {
            int ns = g_col[j + 1];
            xlv = xlp[(size_t)ns * 128 + tid];
        }
        float4 t;
        t.x = lrelu(cur.x + xrv.x);
        t.y = lrelu(cur.y + xrv.y);
        t.z = lrelu(cur.z + xrv.z);
        t.w = lrelu(cur.w + xrv.w);
        float e = t.x * av.x + t.y * av.y + t.z * av.z + t.w * av.w;
        e += __shfl_xor_sync(0xffffffffu, e, 1, 16);
        e += __shfl_xor_sync(0xffffffffu, e, 2, 16);
        e += __shfl_xor_sync(0xffffffffu, e, 4, 16);
        e += __shfl_xor_sync(0xffffffffu, e, 8, 16);

        float nm = fmaxf(m, e);
        float sc = __expf(m - nm);
        float w  = __expf(e - nm);
        s = s * sc + w;
        acc.x = acc.x * sc + w * cur.x;
        acc.y = acc.y * sc + w * cur.y;
        acc.z = acc.z * sc + w * cur.z;
        acc.w = acc.w * sc + w * cur.w;
        m = nm;
    }
    float inv = 1.f / s;
    float4 o;
    o.x = fmaxf(acc.x * inv + bv.x, 0.f);
    o.y = fmaxf(acc.y * inv + bv.y, 0.f);
    o.z = fmaxf(acc.z * inv + bv.z, 0.f);
    o.w = fmaxf(acc.w * inv + bv.w, 0.f);
    reinterpret_cast<float4*>(hout + (size_t)node * HD)[tid] = o;
}

/* --------------- layer-2 weight transpose: [512][16]x2 -> [32][512] ------ */
__global__ void k_wt(const float* __restrict__ Wl, const float* __restrict__ Wr) {
    int i = blockIdx.x * 256 + threadIdx.x;
    if (i >= HD * NC) return;
    int k = i >> 4, c = i & 15;
    g_Wt[(size_t)c * HD + k] = Wl[i];
    g_Wt[(size_t)(16 + c) * HD + k] = Wr[i];
}

/* ----------------- layer-2 linear via transposed weights ----------------- */
/* one warp per node; lanes 0-15 -> xl2 cols, 16-31 -> xr2 cols.
   k-paired f32x2 dot of hsm row (broadcast) with Wt row (contiguous). */
__global__ void __launch_bounds__(256)
k_lin2(const float* __restrict__ h,
       const float* __restrict__ bl, const float* __restrict__ br_,
       float* __restrict__ xl2, float* __restrict__ xr2)
{
    __shared__ __align__(16) float hsm[8][HD];
    int li = threadIdx.x >> 5, lane = threadIdx.x & 31;
    int node = blockIdx.x * 8 + li;
    if (node < NN) {
        const float4* hr = reinterpret_cast<const float4*>(h + (size_t)node * HD);
        float4* ds = reinterpret_cast<float4*>(hsm[li]);
        #pragma unroll
        for (int i = 0; i < 4; i++) ds[lane + 32 * i] = hr[lane + 32 * i];
    }
    __syncwarp();
    if (node >= NN) return;

    const ulonglong2* wp = reinterpret_cast<const ulonglong2*>(g_Wt + (size_t)lane * HD);
    const ulonglong2* hp = reinterpret_cast<const ulonglong2*>(hsm[li]);
    unsigned long long acc0 = 0ull, acc1 = 0ull;
    #pragma unroll 8
    for (int i = 0; i < HD / 4; i++) {
        ulonglong2 hv = hp[i];
        ulonglong2 wv = wp[i];
        fma2(acc0, hv.x, wv.x);
        fma2(acc1, hv.y, wv.y);
    }
    float2 f0 = upk2(acc0), f1 = upk2(acc1);
    float r = (f0.x + f0.y) + (f1.x + f1.y);
    int col = lane & 15;
    if (lane < 16) xl2[(size_t)node * NC + col] = r + bl[col];
    else           xr2[(size_t)node * NC + col] = r + br_[col];
}

/* --------------------- layer-2 GATv2 (H=1, D=16) -------------------------- */
__global__ void __launch_bounds__(256)
k_gat2(const float* __restrict__ xl, const float* __restrict__ xr,
       const float* __restrict__ att, const float* __restrict__ bias,
       float* __restrict__ out)
{
    int node = blockIdx.x * 16 + (threadIdx.x >> 4);
    int lane = threadIdx.x & 15;
    if (node >= NN) return;

    float xrv = xr[(size_t)node * NC + lane];
    float av  = att[lane];

    int jb = g_rowptr[node], je = g_rowptr[node + 1];
    float m = -1e30f, s = 0.f, acc = 0.f;

    for (int j = jb; j < je; j++) {
        int src = g_col[j];
        float xlv = xl[(size_t)src * NC + lane];
        float t = lrelu(xlv + xrv);
        float e = t * av;
        e += __shfl_xor_sync(0xffffffffu, e, 1, 16);
        e += __shfl_xor_sync(0xffffffffu, e, 2, 16);
        e += __shfl_xor_sync(0xffffffffu, e, 4, 16);
        e += __shfl_xor_sync(0xffffffffu, e, 8, 16);

        float nm = fmaxf(m, e);
        float sc = __expf(m - nm);
        float w  = __expf(e - nm);
        s = s * sc + w;
        acc = acc * sc + w * xlv;
        m = nm;
    }
    out[(size_t)node * NC + lane] = acc / s + bias[lane];
}

/* ------------------------------- launch ---------------------------------- */
extern "C" void kernel_launch(void* const* d_in, const int* in_sizes, int n_in,
                              void* d_out, int out_size)
{
    const float* x     = (const float*)d_in[0];
    const void*  ei    = d_in[1];
    const float* W_l1  = (const float*)d_in[2];
    const float* b_l1  = (const float*)d_in[3];
    const float* W_r1  = (const float*)d_in[4];
    const float* b_r1  = (const float*)d_in[5];
    const float* att1  = (const float*)d_in[6];
    const float* bias1 = (const float*)d_in[7];
    const float* W_l2  = (const float*)d_in[8];
    const float* b_l2  = (const float*)d_in[9];
    const float* W_r2  = (const float*)d_in[10];
    const float* b_r2  = (const float*)d_in[11];
    const float* att2  = (const float*)d_in[12];
    const float* bias2 = (const float*)d_in[13];
    float* out = (float*)d_out;

    float *xl1, *xr1, *h, *xl2, *xr2;
    cudaGetSymbolAddress((void**)&xl1, g_xl1);
    cudaGetSymbolAddress((void**)&xr1, g_xr1);
    cudaGetSymbolAddress((void**)&h,   g_h);
    cudaGetSymbolAddress((void**)&xl2, g_xl2);
    cudaGetSymbolAddress((void**)&xr2, g_xr2);

    k_detect<<<1, 1024>>>((const int*)ei);
    k_zero_deg<<<(NN + 255) / 256, 256>>>();
    k_hist<<<(ET + 255) / 256, 256>>>(ei);
    k_scan<<<1, 1024>>>();
    k_scatter<<<(ET + 255) / 256, 256>>>(ei);

    dim3 g1((NN + BM - 1) / BM, HD / BN, 2);
    k_sgemm2<<<g1, 256>>>(x, NN, HD, F1, W_l1, b_l1, xl1, W_r1, b_r1, xr1);

    k_wt<<<(HD * NC + 255) / 256, 256>>>(W_l2, W_r2);

    k_gat1<<<NN, 128>>>(xl1, xr1, att1, bias1, h);

    k_lin2<<<(NN + 7) / 8, 256>>>(h, b_l2, b_r2, xl2, xr2);

    k_gat2<<<(NN + 15) / 16, 256>>>(xl2, xr2, att2, bias2, out);
}

// round 4
// speedup vs baseline: 1.2816x; 1.2816x over previous
#include <cuda_runtime.h>
#include <cuda_bf16.h>
#include <cstdint>

#define NN 20000
#define NNP 20096   /* padded to 157*128 */
#define NE 320000
#define ET 340000
#define F1 256
#define KK3 768     /* 3*F1: [Ah|Ah|Al] x [Bh|Bl|Bh] */
#define HD 512
#define NC 16
#define NEG 0.2f

/* ----------------------------- device scratch ---------------------------- */
__device__ float g_xl1[NN * HD];
__device__ float g_xr1[NN * HD];
__device__ float g_h  [NN * HD];
__device__ float g_xl2[NN * NC];
__device__ float g_xr2[NN * NC];
__device__ float g_Wt [32 * HD];
__device__ __nv_bfloat16 g_Abf[(size_t)NNP * KK3];
__device__ __nv_bfloat16 g_Bbf[2 * HD * KK3];   /* [z][n][k3] n-major */
__device__ int   g_deg[NN];
__device__ int   g_rowptr[NN + 1];
__device__ int   g_wp[NN];
__device__ int   g_col[ET];
__device__ int   g_is64;

/* --------------------------- helpers ------------------------------------- */
__device__ __forceinline__ float lrelu(float x) { return x > 0.f ? x : NEG * x; }

__device__ __forceinline__ unsigned long long pk2(float x, float y) {
    unsigned long long r;
    asm("mov.b64 %0, {%1, %2};" : "=l"(r)
        : "r"(__float_as_uint(x)), "r"(__float_as_uint(y)));
    return r;
}
__device__ __forceinline__ void fma2(unsigned long long& c,
                                     unsigned long long a, unsigned long long b) {
    asm("fma.rn.f32x2 %0, %1, %2, %0;" : "+l"(c) : "l"(a), "l"(b));
}
__device__ __forceinline__ float2 upk2(unsigned long long v) {
    unsigned lo, hi;
    asm("mov.b64 {%0, %1}, %2;" : "=r"(lo), "=r"(hi) : "l"(v));
    return make_float2(__uint_as_float(lo), __uint_as_float(hi));
}

__device__ __forceinline__ int edge_val(const void* ei, int idx) {
    if (g_is64) return (int)(((const long long*)ei)[idx]);
    return ((const int*)ei)[idx];
}

__device__ __forceinline__ uint32_t smem_u32(const void* p) {
    uint32_t a;
    asm("{ .reg .u64 t; cvta.to.shared.u64 t, %1; cvt.u32.u64 %0, t; }"
        : "=r"(a) : "l"(p));
    return a;
}

__device__ __forceinline__ void cpa16(uint32_t dst, const void* src) {
    asm volatile("cp.async.cg.shared.global [%0], [%1], 16;"
                 :: "r"(dst), "l"(src) : "memory");
}
#define CPA_COMMIT() asm volatile("cp.async.commit_group;" ::: "memory")
#define CPA_WAIT(n)  asm volatile("cp.async.wait_group %0;" :: "n"(n) : "memory")

static __device__ __forceinline__ uint32_t sw128(uint32_t off) {
    return off ^ ((off >> 3) & 0x70);
}

#define LDSM4(r0, r1, r2, r3, a) \
    asm volatile("ldmatrix.sync.aligned.m8n8.x4.shared.b16 {%0,%1,%2,%3}, [%4];" \
                 : "=r"(r0), "=r"(r1), "=r"(r2), "=r"(r3) : "r"(a))

__device__ __forceinline__ void mma16816(float* d, const uint32_t* a,
                                         uint32_t b0, uint32_t b1) {
    asm volatile(
        "mma.sync.aligned.m16n8k16.row.col.f32.bf16.bf16.f32 "
        "{%0,%1,%2,%3}, {%4,%5,%6,%7}, {%8,%9}, {%0,%1,%2,%3};"
        : "+f"(d[0]), "+f"(d[1]), "+f"(d[2]), "+f"(d[3])
        : "r"(a[0]), "r"(a[1]), "r"(a[2]), "r"(a[3]), "r"(b0), "r"(b1));
}

/* --------------------------- dtype detection ----------------------------- */
__global__ void k_detect(const int* __restrict__ ei32) {
    __shared__ int s;
    if (threadIdx.x == 0) s = 0;
    __syncthreads();
    int v = ei32[threadIdx.x * 2 + 1];
    if (v != 0) atomicOr(&s, 1);
    __syncthreads();
    if (threadIdx.x == 0) g_is64 = (s == 0) ? 1 : 0;
}

/* ------------------------------- CSR build ------------------------------- */
__global__ void k_zero_deg() {
    int i = blockIdx.x * blockDim.x + threadIdx.x;
    if (i < NN) g_deg[i] = 0;
}

__global__ void k_hist(const void* __restrict__ ei) {
    int i = blockIdx.x * blockDim.x + threadIdx.x;
    if (i >= ET) return;
    int dst = (i < NE) ? edge_val(ei, NE + i) : (i - NE);
    atomicAdd(&g_deg[dst], 1);
}

/* single block, 1024 threads, coalesced via 80KB dynamic smem */
__global__ void k_scan() {
    extern __shared__ int sdeg[];
    __shared__ int wsum[32];
    int tid = threadIdx.x, lane = tid & 31, wid = tid >> 5;

    for (int i = tid; i < NN; i += 1024) sdeg[i] = g_deg[i];
    __syncthreads();

    int base = tid * 20;
    int loc[20];
    int s = 0;
    #pragma unroll
    for (int i = 0; i < 20; i++) {
        int v = (base + i < NN) ? sdeg[base + i] : 0;
        loc[i] = s; s += v;
    }
    int ws = s;
    #pragma unroll
    for (int off = 1; off < 32; off <<= 1) {
        int t = __shfl_up_sync(0xffffffffu, ws, off);
        if (lane >= off) ws += t;
    }
    if (lane == 31) wsum[wid] = ws;
    __syncthreads();
    if (wid == 0) {
        int v = wsum[lane];
        int x = v;
        #pragma unroll
        for (int off = 1; off < 32; off <<= 1) {
            int t = __shfl_up_sync(0xffffffffu, x, off);
            if (lane >= off) x += t;
        }
        wsum[lane] = x - v;
    }
    __syncthreads();
    int thr_excl = wsum[wid] + ws - s;
    #pragma unroll
    for (int i = 0; i < 20; i++) {
        int idx = base + i;
        if (idx < NN) sdeg[idx] = thr_excl + loc[i];
    }
    __syncthreads();
    for (int i = tid; i < NN; i += 1024) {
        int e = sdeg[i];
        g_rowptr[i] = e;
        g_wp[i] = e;
    }
    if (tid == 0) g_rowptr[NN] = ET;
}

__global__ void k_scatter(const void* __restrict__ ei) {
    int i = blockIdx.x * blockDim.x + threadIdx.x;
    if (i >= ET) return;
    int src, dst;
    if (i < NE) { src = edge_val(ei, i); dst = edge_val(ei, NE + i); }
    else        { src = i - NE; dst = i - NE; }
    int pos = atomicAdd(&g_wp[dst], 1);
    g_col[pos] = src;
}

/* ------------------------- bf16 hi/lo splits ------------------------------ */
/* A' row m (len 768): [hi(256) | hi(256) | lo(256)]                          */
__global__ void k_splitA(const float* __restrict__ x) {
    int i = blockIdx.x * 256 + threadIdx.x;     /* float4 index */
    if (i >= NNP * (F1 / 4)) return;
    int m = i >> 6;
    int c4 = i & 63;                            /* float4 within row */
    float4 v = make_float4(0.f, 0.f, 0.f, 0.f);
    if (m < NN) v = reinterpret_cast<const float4*>(x)[i];
    __nv_bfloat16 hx = __float2bfloat16_rn(v.x);
    __nv_bfloat16 hy = __float2bfloat16_rn(v.y);
    __nv_bfloat16 hz = __float2bfloat16_rn(v.z);
    __nv_bfloat16 hw = __float2bfloat16_rn(v.w);
    __nv_bfloat16 lx = __float2bfloat16_rn(v.x - __bfloat162float(hx));
    __nv_bfloat16 ly = __float2bfloat16_rn(v.y - __bfloat162float(hy));
    __nv_bfloat16 lz = __float2bfloat16_rn(v.z - __bfloat162float(hz));
    __nv_bfloat16 lw = __float2bfloat16_rn(v.w - __bfloat162float(hw));
    __nv_bfloat162 h01, h23, l01, l23;
    h01.x = hx; h01.y = hy; h23.x = hz; h23.y = hw;
    l01.x = lx; l01.y = ly; l23.x = lz; l23.y = lw;
    size_t rb = (size_t)m * KK3 + c4 * 4;
    __nv_bfloat162* p0 = reinterpret_cast<__nv_bfloat162*>(&g_Abf[rb]);
    __nv_bfloat162* p1 = reinterpret_cast<__nv_bfloat162*>(&g_Abf[rb + F1]);
    __nv_bfloat162* p2 = reinterpret_cast<__nv_bfloat162*>(&g_Abf[rb + 2 * F1]);
    p0[0] = h01; p0[1] = h23;
    p1[0] = h01; p1[1] = h23;
    p2[0] = l01; p2[1] = l23;
}

/* B' row n (len 768): [hi(256) | lo(256) | hi(256)]; W is [256][512] k-major */
__global__ void k_splitB(const float* __restrict__ W0, const float* __restrict__ W1) {
    int i = blockIdx.x * 256 + threadIdx.x;
    if (i >= 2 * HD * F1) return;
    int z = i >> 17;
    int r = i & 131071;
    int n = r >> 8, k = r & 255;
    const float* W = z ? W1 : W0;
    float v = W[(size_t)k * HD + n];
    __nv_bfloat16 h = __float2bfloat16_rn(v);
    __nv_bfloat16 l = __float2bfloat16_rn(v - __bfloat162float(h));
    size_t base = (size_t)z * HD * KK3 + (size_t)n * KK3;
    g_Bbf[base + k] = h;
    g_Bbf[base + F1 + k] = l;
    g_Bbf[base + 2 * F1 + k] = h;
}

/* -------------------- 3xBF16 HMMA GEMM ------------------------------------ */
/* C[z][NNP][512] = A'[NNP][768] @ B'[z][512][768]^T, tiles 128x128xBK64.    */
#define BK 64
#define NIT (KK3 / BK)        /* 12 */
#define STG 16384             /* one operand tile: 128 rows x 128B */

__global__ void __launch_bounds__(256, 2)
k_hmma(const float* __restrict__ b0, const float* __restrict__ b1)
{
    extern __shared__ char dyn[];
    uint32_t SB = (smem_u32(dyn) + 1023u) & ~1023u;

    int tid = threadIdx.x;
    int lane = tid & 31, wid = tid >> 5;
    int warp_m = wid >> 2, warp_n = wid & 3;   /* 2 x 4 warp grid */
    int bm = blockIdx.x * 128;
    int bn = blockIdx.y * 128;
    int z  = blockIdx.z;

    const __nv_bfloat16* Asrc = g_Abf + (size_t)bm * KK3;
    const __nv_bfloat16* Bsrc = g_Bbf + (size_t)z * HD * KK3 + (size_t)bn * KK3;

    /* loader: thread does 4 chunks per operand */
    int lr = tid >> 1;                 /* 0..127: row pair granularity */
    int lc = (tid & 1) << 2;           /* chunk 0 or 4 */
    auto load_tiles = [&](int it, int s) {
        int k0 = it * BK;
        uint32_t Ab = SB + (uint32_t)s * (2 * STG);
        uint32_t Bb = Ab + STG;
        #pragma unroll
        for (int i = 0; i < 4; i++) {
            int cj = lc + i;
            cpa16(Ab + sw128((uint32_t)(lr * 128 + cj * 16)),
                  Asrc + (size_t)lr * KK3 + k0 + cj * 8);
            cpa16(Bb + sw128((uint32_t)(lr * 128 + cj * 16)),
                  Bsrc + (size_t)lr * KK3 + k0 + cj * 8);
        }
        CPA_COMMIT();
    };

    float d[4][4][4];
    #pragma unroll
    for (int i = 0; i < 4; i++)
        #pragma unroll
        for (int j = 0; j < 4; j++)
            #pragma unroll
            for (int q = 0; q < 4; q++) d[i][j][q] = 0.f;

    load_tiles(0, 0);

    int l15 = lane & 15;
    int kb_lane = (lane & 16);   /* +16B for upper half k */

    #pragma unroll 1
    for (int it = 0; it < NIT; it++) {
        if (it + 1 < NIT) { load_tiles(it + 1, (it + 1) & 1); CPA_WAIT(1); }
        else              { CPA_WAIT(0); }
        __syncthreads();

        uint32_t Ab = SB + (uint32_t)(it & 1) * (2 * STG);
        uint32_t Bb = Ab + STG;

        #pragma unroll
        for (int ks = 0; ks < 4; ks++) {
            uint32_t a[4][4];
            #pragma unroll
            for (int mi = 0; mi < 4; mi++) {
                uint32_t off = (uint32_t)((warp_m * 64 + mi * 16 + l15) * 128
                                          + ks * 32 + kb_lane);
                LDSM4(a[mi][0], a[mi][1], a[mi][2], a[mi][3], Ab + sw128(off));
            }
            uint32_t bf[2][4];
            #pragma unroll
            for (int bj = 0; bj < 2; bj++) {
                uint32_t off = (uint32_t)((warp_n * 32 + bj * 16 + l15) * 128
                                          + ks * 32 + kb_lane);
                LDSM4(bf[bj][0], bf[bj][1], bf[bj][2], bf[bj][3], Bb + sw128(off));
            }
            #pragma unroll
            for (int mi = 0; mi < 4; mi++)
                #pragma unroll
                for (int nj = 0; nj < 4; nj++) {
                    int bj = nj >> 1, sel = nj & 1;
                    mma16816(d[mi][nj], a[mi], bf[bj][sel], bf[bj][sel + 2]);
                }
        }
        __syncthreads();
    }

    /* epilogue */
    float*       C    = z ? g_xr1 : g_xl1;
    const float* bias = z ? b1 : b0;
    int colb = bn + warp_n * 32 + (lane & 3) * 2;
    int rowb = bm + warp_m * 64 + (lane >> 2);
    #pragma unroll
    for (int nj = 0; nj < 4; nj++) {
        int col = colb + nj * 8;
        float2 bv = *reinterpret_cast<const float2*>(bias + col);
        #pragma unroll
        for (int mi = 0; mi < 4; mi++) {
            int r0 = rowb + mi * 16;
            if (r0 < NN) {
                float2 o = make_float2(d[mi][nj][0] + bv.x, d[mi][nj][1] + bv.y);
                *reinterpret_cast<float2*>(C + (size_t)r0 * HD + col) = o;
            }
            if (r0 + 8 < NN) {
                float2 o = make_float2(d[mi][nj][2] + bv.x, d[mi][nj][3] + bv.y);
                *reinterpret_cast<float2*>(C + (size_t)(r0 + 8) * HD + col) = o;
            }
        }
    }
}

/* -------------------- layer-1 GATv2 (flash-style softmax) ---------------- */
__global__ void __launch_bounds__(128)
k_gat1(const float* __restrict__ xl, const float* __restrict__ xr,
       const float* __restrict__ att, const float* __restrict__ bias,
       float* __restrict__ hout)
{
    int node = blockIdx.x;
    int tid = threadIdx.x;

    float4 xrv = reinterpret_cast<const float4*>(xr + (size_t)node * HD)[tid];
    float4 av  = reinterpret_cast<const float4*>(att)[tid];
    float4 bv  = reinterpret_cast<const float4*>(bias)[tid];

    int jb = g_rowptr[node], je = g_rowptr[node + 1];

    float m = -1e30f, s = 0.f;
    float4 acc = make_float4(0.f, 0.f, 0.f, 0.f);

    const float4* xlp = reinterpret_cast<const float4*>(xl);
    float4 xlv = make_float4(0.f, 0.f, 0.f, 0.f);
    if (jb < je) {
        int src0 = g_col[jb];
        xlv = xlp[(size_t)src0 * 128 + tid];
    }
    for (int j = jb; j < je; j++) {
        float4 cur = xlv;
        if (j + 1 < je) {
            int ns = g_col[j + 1];
            xlv = xlp[(size_t)ns * 128 + tid];
        }
        float4 t;
        t.x = lrelu(cur.x + xrv.x);
        t.y = lrelu(cur.y + xrv.y);
        t.z = lrelu(cur.z + xrv.z);
        t.w = lrelu(cur.w + xrv.w);
        float e = t.x * av.x + t.y * av.y + t.z * av.z + t.w * av.w;
        e += __shfl_xor_sync(0xffffffffu, e, 1, 16);
        e += __shfl_xor_sync(0xffffffffu, e, 2, 16);
        e += __shfl_xor_sync(0xffffffffu, e, 4, 16);
        e += __shfl_xor_sync(0xffffffffu, e, 8, 16);

        float nm = fmaxf(m, e);
        float sc = __expf(m - nm);
        float w  = __expf(e - nm);
        s = s * sc + w;
        acc.x = acc.x * sc + w * cur.x;
        acc.y = acc.y * sc + w * cur.y;
        acc.z = acc.z * sc + w * cur.z;
        acc.w = acc.w * sc + w * cur.w;
        m = nm;
    }
    float inv = 1.f / s;
    float4 o;
    o.x = fmaxf(acc.x * inv + bv.x, 0.f);
    o.y = fmaxf(acc.y * inv + bv.y, 0.f);
    o.z = fmaxf(acc.z * inv + bv.z, 0.f);
    o.w = fmaxf(acc.w * inv + bv.w, 0.f);
    reinterpret_cast<float4*>(hout + (size_t)node * HD)[tid] = o;
}

/* --------------- layer-2 weight transpose -------------------------------- */
__global__ void k_wt(const float* __restrict__ Wl, const float* __restrict__ Wr) {
    int i = blockIdx.x * 256 + threadIdx.x;
    if (i >= HD * NC) return;
    int k = i >> 4, c = i & 15;
    g_Wt[(size_t)c * HD + k] = Wl[i];
    g_Wt[(size_t)(16 + c) * HD + k] = Wr[i];
}

/* ----------------- layer-2 linear ----------------------------------------- */
__global__ void __launch_bounds__(256)
k_lin2(const float* __restrict__ h,
       const float* __restrict__ bl, const float* __restrict__ br_,
       float* __restrict__ xl2, float* __restrict__ xr2)
{
    __shared__ __align__(16) float hsm[8][HD];
    int li = threadIdx.x >> 5, lane = threadIdx.x & 31;
    int node = blockIdx.x * 8 + li;
    if (node < NN) {
        const float4* hr = reinterpret_cast<const float4*>(h + (size_t)node * HD);
        float4* ds = reinterpret_cast<float4*>(hsm[li]);
        #pragma unroll
        for (int i = 0; i < 4; i++) ds[lane + 32 * i] = hr[lane + 32 * i];
    }
    __syncwarp();
    if (node >= NN) return;

    const ulonglong2* wp = reinterpret_cast<const ulonglong2*>(g_Wt + (size_t)lane * HD);
    const ulonglong2* hp = reinterpret_cast<const ulonglong2*>(hsm[li]);
    unsigned long long acc0 = 0ull, acc1 = 0ull;
    #pragma unroll 8
    for (int i = 0; i < HD / 4; i++) {
        ulonglong2 hv = hp[i];
        ulonglong2 wv = wp[i];
        fma2(acc0, hv.x, wv.x);
        fma2(acc1, hv.y, wv.y);
    }
    float2 f0 = upk2(acc0), f1 = upk2(acc1);
    float r = (f0.x + f0.y) + (f1.x + f1.y);
    int col = lane & 15;
    if (lane < 16) xl2[(size_t)node * NC + col] = r + bl[col];
    else           xr2[(size_t)node * NC + col] = r + br_[col];
}

/* --------------------- layer-2 GATv2 -------------------------------------- */
__global__ void __launch_bounds__(256)
k_gat2(const float* __restrict__ xl, const float* __restrict__ xr,
       const float* __restrict__ att, const float* __restrict__ bias,
       float* __restrict__ out)
{
    int node = blockIdx.x * 16 + (threadIdx.x >> 4);
    int lane = threadIdx.x & 15;
    if (node >= NN) return;

    float xrv = xr[(size_t)node * NC + lane];
    float av  = att[lane];

    int jb = g_rowptr[node], je = g_rowptr[node + 1];
    float m = -1e30f, s = 0.f, acc = 0.f;

    for (int j = jb; j < je; j++) {
        int src = g_col[j];
        float xlv = xl[(size_t)src * NC + lane];
        float t = lrelu(xlv + xrv);
        float e = t * av;
        e += __shfl_xor_sync(0xffffffffu, e, 1, 16);
        e += __shfl_xor_sync(0xffffffffu, e, 2, 16);
        e += __shfl_xor_sync(0xffffffffu, e, 4, 16);
        e += __shfl_xor_sync(0xffffffffu, e, 8, 16);

        float nm = fmaxf(m, e);
        float sc = __expf(m - nm);
        float w  = __expf(e - nm);
        s = s * sc + w;
        acc = acc * sc + w * xlv;
        m = nm;
    }
    out[(size_t)node * NC + lane] = acc / s + bias[lane];
}

/* ------------------------------- launch ---------------------------------- */
extern "C" void kernel_launch(void* const* d_in, const int* in_sizes, int n_in,
                              void* d_out, int out_size)
{
    const float* x     = (const float*)d_in[0];
    const void*  ei    = d_in[1];
    const float* W_l1  = (const float*)d_in[2];
    const float* b_l1  = (const float*)d_in[3];
    const float* W_r1  = (const float*)d_in[4];
    const float* b_r1  = (const float*)d_in[5];
    const float* att1  = (const float*)d_in[6];
    const float* bias1 = (const float*)d_in[7];
    const float* W_l2  = (const float*)d_in[8];
    const float* b_l2  = (const float*)d_in[9];
    const float* W_r2  = (const float*)d_in[10];
    const float* b_r2  = (const float*)d_in[11];
    const float* att2  = (const float*)d_in[12];
    const float* bias2 = (const float*)d_in[13];
    float* out = (float*)d_out;

    float *xl1, *xr1, *h, *xl2, *xr2;
    cudaGetSymbolAddress((void**)&xl1, g_xl1);
    cudaGetSymbolAddress((void**)&xr1, g_xr1);
    cudaGetSymbolAddress((void**)&h,   g_h);
    cudaGetSymbolAddress((void**)&xl2, g_xl2);
    cudaGetSymbolAddress((void**)&xr2, g_xr2);

    cudaFuncSetAttribute(k_scan, cudaFuncAttributeMaxDynamicSharedMemorySize, NN * 4);
    cudaFuncSetAttribute(k_hmma, cudaFuncAttributeMaxDynamicSharedMemorySize, 4 * STG + 1024);

    k_splitA<<<(NNP * (F1 / 4) + 255) / 256, 256>>>(x);
    k_splitB<<<(2 * HD * F1 + 255) / 256, 256>>>(W_l1, W_r1);

    k_detect<<<1, 1024>>>((const int*)ei);
    k_zero_deg<<<(NN + 255) / 256, 256>>>();
    k_hist<<<(ET + 255) / 256, 256>>>(ei);
    k_scan<<<1, 1024, NN * 4>>>();
    k_scatter<<<(ET + 255) / 256, 256>>>(ei);

    dim3 gm(NNP / 128, HD / 128, 2);
    k_hmma<<<gm, 256, 4 * STG + 1024>>>(b_l1, b_r1);

    k_wt<<<(HD * NC + 255) / 256, 256>>>(W_l2, W_r2);

    k_gat1<<<NN, 128>>>(xl1, xr1, att1, bias1, h);

    k_lin2<<<(NN + 7) / 8, 256>>>(h, b_l2, b_r2, xl2, xr2);

    k_gat2<<<(NN + 15) / 16, 256>>>(xl2, xr2, att2, bias2, out);
}

// round 5
// speedup vs baseline: 2.2510x; 1.7563x over previous
#include <cuda_runtime.h>
#include <cuda_bf16.h>
#include <cstdint>

#define NN 20000
#define NNP 20096   /* padded to 157*128 */
#define NE 320000
#define ET 340000
#define F1 256
#define KK3 768     /* 3*F1: [Ah|Ah|Al] x [Bh|Bl|Bh] */
#define HD 512
#define NC 16
#define NEG 0.2f

/* ----------------------------- device scratch ---------------------------- */
__device__ float g_xl1[NN * HD];
__device__ float g_xr1[NN * HD];
__device__ float g_h  [NN * HD];
__device__ float g_xl2[NN * NC];
__device__ float g_xr2[NN * NC];
__device__ float g_Wt2[HD * 32];                /* [k][32] k-major fused W2 */
__device__ __nv_bfloat16 g_Abf[(size_t)NNP * KK3];
__device__ __nv_bfloat16 g_Bbf[2 * HD * KK3];   /* [z][n][k3] n-major */
__device__ int   g_deg[NN];
__device__ int   g_rowptr[NN + 1];
__device__ int   g_wp[NN];
__device__ int   g_col[ET];
__device__ int   g_is64;

/* --------------------------- helpers ------------------------------------- */
__device__ __forceinline__ float lrelu(float x) { return x > 0.f ? x : NEG * x; }

__device__ __forceinline__ unsigned long long pk2(float x, float y) {
    unsigned long long r;
    asm("mov.b64 %0, {%1, %2};" : "=l"(r)
        : "r"(__float_as_uint(x)), "r"(__float_as_uint(y)));
    return r;
}
__device__ __forceinline__ void fma2(unsigned long long& c,
                                     unsigned long long a, unsigned long long b) {
    asm("fma.rn.f32x2 %0, %1, %2, %0;" : "+l"(c) : "l"(a), "l"(b));
}
__device__ __forceinline__ float2 upk2(unsigned long long v) {
    unsigned lo, hi;
    asm("mov.b64 {%0, %1}, %2;" : "=r"(lo), "=r"(hi) : "l"(v));
    return make_float2(__uint_as_float(lo), __uint_as_float(hi));
}

__device__ __forceinline__ int edge_val(const void* ei, int idx) {
    if (g_is64) return (int)(((const long long*)ei)[idx]);
    return ((const int*)ei)[idx];
}

__device__ __forceinline__ uint32_t smem_u32(const void* p) {
    uint32_t a;
    asm("{ .reg .u64 t; cvta.to.shared.u64 t, %1; cvt.u32.u64 %0, t; }"
        : "=r"(a) : "l"(p));
    return a;
}

__device__ __forceinline__ void cpa16(uint32_t dst, const void* src) {
    asm volatile("cp.async.cg.shared.global [%0], [%1], 16;"
                 :: "r"(dst), "l"(src) : "memory");
}
#define CPA_COMMIT() asm volatile("cp.async.commit_group;" ::: "memory")
#define CPA_WAIT(n)  asm volatile("cp.async.wait_group %0;" :: "n"(n) : "memory")

static __device__ __forceinline__ uint32_t sw128(uint32_t off) {
    return off ^ ((off >> 3) & 0x70);
}

#define LDSM4(r0, r1, r2, r3, a) \
    asm volatile("ldmatrix.sync.aligned.m8n8.x4.shared.b16 {%0,%1,%2,%3}, [%4];" \
                 : "=r"(r0), "=r"(r1), "=r"(r2), "=r"(r3) : "r"(a))

__device__ __forceinline__ void mma16816(float* d, const uint32_t* a,
                                         uint32_t b0, uint32_t b1) {
    asm volatile(
        "mma.sync.aligned.m16n8k16.row.col.f32.bf16.bf16.f32 "
        "{%0,%1,%2,%3}, {%4,%5,%6,%7}, {%8,%9}, {%0,%1,%2,%3};"
        : "+f"(d[0]), "+f"(d[1]), "+f"(d[2]), "+f"(d[3])
        : "r"(a[0]), "r"(a[1]), "r"(a[2]), "r"(a[3]), "r"(b0), "r"(b1));
}

/* ------------- prep0: fused A split + B split + W2 transpose -------------- */
#define W_A (NNP * (F1 / 4))          /* 1286144 float4 items */
#define W_B (2 * HD * F1)             /* 262144 */
#define W_W (HD * NC)                 /* 8192 */

__global__ void k_prep0(const float* __restrict__ x,
                        const float* __restrict__ W0, const float* __restrict__ W1,
                        const float* __restrict__ Wl2, const float* __restrict__ Wr2)
{
    int idx = blockIdx.x * 256 + threadIdx.x;
    if (idx < W_A) {
        int i = idx;
        int m = i >> 6;
        int c4 = i & 63;
        float4 v = make_float4(0.f, 0.f, 0.f, 0.f);
        if (m < NN) v = reinterpret_cast<const float4*>(x)[i];
        __nv_bfloat16 hx = __float2bfloat16_rn(v.x);
        __nv_bfloat16 hy = __float2bfloat16_rn(v.y);
        __nv_bfloat16 hz = __float2bfloat16_rn(v.z);
        __nv_bfloat16 hw = __float2bfloat16_rn(v.w);
        __nv_bfloat16 lx = __float2bfloat16_rn(v.x - __bfloat162float(hx));
        __nv_bfloat16 ly = __float2bfloat16_rn(v.y - __bfloat162float(hy));
        __nv_bfloat16 lz = __float2bfloat16_rn(v.z - __bfloat162float(hz));
        __nv_bfloat16 lw = __float2bfloat16_rn(v.w - __bfloat162float(hw));
        __nv_bfloat162 h01, h23, l01, l23;
        h01.x = hx; h01.y = hy; h23.x = hz; h23.y = hw;
        l01.x = lx; l01.y = ly; l23.x = lz; l23.y = lw;
        size_t rb = (size_t)m * KK3 + c4 * 4;
        __nv_bfloat162* p0 = reinterpret_cast<__nv_bfloat162*>(&g_Abf[rb]);
        __nv_bfloat162* p1 = reinterpret_cast<__nv_bfloat162*>(&g_Abf[rb + F1]);
        __nv_bfloat162* p2 = reinterpret_cast<__nv_bfloat162*>(&g_Abf[rb + 2 * F1]);
        p0[0] = h01; p0[1] = h23;
        p1[0] = h01; p1[1] = h23;
        p2[0] = l01; p2[1] = l23;
    } else if (idx < W_A + W_B) {
        int i = idx - W_A;
        int z = i >> 17;
        int r = i & 131071;
        int n = r >> 8, k = r & 255;
        const float* W = z ? W1 : W0;
        float v = W[(size_t)k * HD + n];
        __nv_bfloat16 h = __float2bfloat16_rn(v);
        __nv_bfloat16 l = __float2bfloat16_rn(v - __bfloat162float(h));
        size_t base = (size_t)z * HD * KK3 + (size_t)n * KK3;
        g_Bbf[base + k] = h;
        g_Bbf[base + F1 + k] = l;
        g_Bbf[base + 2 * F1 + k] = h;
    } else if (idx < W_A + W_B + W_W) {
        int i = idx - W_A - W_B;
        int k = i >> 4, c = i & 15;
        g_Wt2[k * 32 + c]      = Wl2[i];
        g_Wt2[k * 32 + 16 + c] = Wr2[i];
    }
}

/* ------------- prep1: fused dtype detect + zero g_deg --------------------- */
__global__ void k_prep1(const int* __restrict__ ei32) {
    if (blockIdx.x < 79) {
        int i = blockIdx.x * 256 + threadIdx.x;
        if (i < NN) g_deg[i] = 0;
    } else {
        __shared__ int sflag;
        int tid = threadIdx.x;
        if (tid == 0) sflag = 0;
        __syncthreads();
        int bad = 0;
        #pragma unroll
        for (int i = 0; i < 4; i++) bad |= ei32[(tid * 4 + i) * 2 + 1];
        if (bad) atomicOr(&sflag, 1);
        __syncthreads();
        if (tid == 0) g_is64 = (sflag == 0) ? 1 : 0;
    }
}

/* ------------------------------- CSR build ------------------------------- */
__global__ void k_hist(const void* __restrict__ ei) {
    int i = blockIdx.x * blockDim.x + threadIdx.x;
    if (i >= ET) return;
    int dst = (i < NE) ? edge_val(ei, NE + i) : (i - NE);
    atomicAdd(&g_deg[dst], 1);
}

__global__ void k_scan() {
    extern __shared__ int sdeg[];
    __shared__ int wsum[32];
    int tid = threadIdx.x, lane = tid & 31, wid = tid >> 5;

    for (int i = tid; i < NN; i += 1024) sdeg[i] = g_deg[i];
    __syncthreads();

    int base = tid * 20;
    int loc[20];
    int s = 0;
    #pragma unroll
    for (int i = 0; i < 20; i++) {
        int v = (base + i < NN) ? sdeg[base + i] : 0;
        loc[i] = s; s += v;
    }
    int ws = s;
    #pragma unroll
    for (int off = 1; off < 32; off <<= 1) {
        int t = __shfl_up_sync(0xffffffffu, ws, off);
        if (lane >= off) ws += t;
    }
    if (lane == 31) wsum[wid] = ws;
    __syncthreads();
    if (wid == 0) {
        int v = wsum[lane];
        int x = v;
        #pragma unroll
        for (int off = 1; off < 32; off <<= 1) {
            int t = __shfl_up_sync(0xffffffffu, x, off);
            if (lane >= off) x += t;
        }
        wsum[lane] = x - v;
    }
    __syncthreads();
    int thr_excl = wsum[wid] + ws - s;
    #pragma unroll
    for (int i = 0; i < 20; i++) {
        int idx = base + i;
        if (idx < NN) sdeg[idx] = thr_excl + loc[i];
    }
    __syncthreads();
    for (int i = tid; i < NN; i += 1024) {
        int e = sdeg[i];
        g_rowptr[i] = e;
        g_wp[i] = e;
    }
    if (tid == 0) g_rowptr[NN] = ET;
}

__global__ void k_scatter(const void* __restrict__ ei) {
    int i = blockIdx.x * blockDim.x + threadIdx.x;
    if (i >= ET) return;
    int src, dst;
    if (i < NE) { src = edge_val(ei, i); dst = edge_val(ei, NE + i); }
    else        { src = i - NE; dst = i - NE; }
    int pos = atomicAdd(&g_wp[dst], 1);
    g_col[pos] = src;
}

/* -------------------- 3xBF16 HMMA GEMM, 3-stage pipeline ------------------ */
#define BK 64
#define NIT (KK3 / BK)        /* 12 */
#define STG 16384

__global__ void __launch_bounds__(256, 2)
k_hmma(const float* __restrict__ b0, const float* __restrict__ b1)
{
    extern __shared__ char dyn[];
    uint32_t SB = (smem_u32(dyn) + 1023u) & ~1023u;

    int tid = threadIdx.x;
    int lane = tid & 31, wid = tid >> 5;
    int warp_m = wid >> 2, warp_n = wid & 3;
    int bm = blockIdx.x * 128;
    int bn = blockIdx.y * 128;
    int z  = blockIdx.z;

    const __nv_bfloat16* Asrc = g_Abf + (size_t)bm * KK3;
    const __nv_bfloat16* Bsrc = g_Bbf + (size_t)z * HD * KK3 + (size_t)bn * KK3;

    int lr = tid >> 1;
    int lc = (tid & 1) << 2;
    auto load_tiles = [&](int it, int s) {
        int k0 = it * BK;
        uint32_t Ab = SB + (uint32_t)s * (2 * STG);
        uint32_t Bb = Ab + STG;
        #pragma unroll
        for (int i = 0; i < 4; i++) {
            int cj = lc + i;
            cpa16(Ab + sw128((uint32_t)(lr * 128 + cj * 16)),
                  Asrc + (size_t)lr * KK3 + k0 + cj * 8);
            cpa16(Bb + sw128((uint32_t)(lr * 128 + cj * 16)),
                  Bsrc + (size_t)lr * KK3 + k0 + cj * 8);
        }
        CPA_COMMIT();
    };

    float d[4][4][4];
    #pragma unroll
    for (int i = 0; i < 4; i++)
        #pragma unroll
        for (int j = 0; j < 4; j++)
            #pragma unroll
            for (int q = 0; q < 4; q++) d[i][j][q] = 0.f;

    load_tiles(0, 0);
    load_tiles(1, 1);

    int l15 = lane & 15;
    int kb_lane = (lane & 16);

    #pragma unroll 1
    for (int it = 0; it < NIT; it++) {
        if (it + 1 < NIT) { CPA_WAIT(1); } else { CPA_WAIT(0); }
        __syncthreads();
        if (it + 2 < NIT) load_tiles(it + 2, (it + 2) % 3);

        uint32_t Ab = SB + (uint32_t)(it % 3) * (2 * STG);
        uint32_t Bb = Ab + STG;

        #pragma unroll
        for (int ks = 0; ks < 4; ks++) {
            uint32_t a[4][4];
            #pragma unroll
            for (int mi = 0; mi < 4; mi++) {
                uint32_t off = (uint32_t)((warp_m * 64 + mi * 16 + l15) * 128
                                          + ks * 32 + kb_lane);
                LDSM4(a[mi][0], a[mi][1], a[mi][2], a[mi][3], Ab + sw128(off));
            }
            uint32_t bf[2][4];
            #pragma unroll
            for (int bj = 0; bj < 2; bj++) {
                uint32_t off = (uint32_t)((warp_n * 32 + bj * 16 + l15) * 128
                                          + ks * 32 + kb_lane);
                LDSM4(bf[bj][0], bf[bj][1], bf[bj][2], bf[bj][3], Bb + sw128(off));
            }
            #pragma unroll
            for (int mi = 0; mi < 4; mi++)
                #pragma unroll
                for (int nj = 0; nj < 4; nj++) {
                    int bj = nj >> 1, sel = nj & 1;
                    mma16816(d[mi][nj], a[mi], bf[bj][sel], bf[bj][sel + 2]);
                }
        }
        __syncthreads();
    }

    float*       C    = z ? g_xr1 : g_xl1;
    const float* bias = z ? b1 : b0;
    int colb = bn + warp_n * 32 + (lane & 3) * 2;
    int rowb = bm + warp_m * 64 + (lane >> 2);
    #pragma unroll
    for (int nj = 0; nj < 4; nj++) {
        int col = colb + nj * 8;
        float2 bv = *reinterpret_cast<const float2*>(bias + col);
        #pragma unroll
        for (int mi = 0; mi < 4; mi++) {
            int r0 = rowb + mi * 16;
            if (r0 < NN) {
                float2 o = make_float2(d[mi][nj][0] + bv.x, d[mi][nj][1] + bv.y);
                *reinterpret_cast<float2*>(C + (size_t)r0 * HD + col) = o;
            }
            if (r0 + 8 < NN) {
                float2 o = make_float2(d[mi][nj][2] + bv.x, d[mi][nj][3] + bv.y);
                *reinterpret_cast<float2*>(C + (size_t)(r0 + 8) * HD + col) = o;
            }
        }
    }
}

/* -------------------- layer-1 GATv2, 4-edge unrolled ---------------------- */
__device__ __forceinline__ float dot_lrelu(float4 c, float4 xr, float4 av) {
    float tx = lrelu(c.x + xr.x);
    float ty = lrelu(c.y + xr.y);
    float tz = lrelu(c.z + xr.z);
    float tw = lrelu(c.w + xr.w);
    return tx * av.x + ty * av.y + tz * av.z + tw * av.w;
}

__global__ void __launch_bounds__(128)
k_gat1(const float* __restrict__ xl, const float* __restrict__ xr,
       const float* __restrict__ att, const float* __restrict__ bias,
       float* __restrict__ hout)
{
    int node = blockIdx.x;
    int tid = threadIdx.x;

    float4 xrv = reinterpret_cast<const float4*>(xr + (size_t)node * HD)[tid];
    float4 av  = reinterpret_cast<const float4*>(att)[tid];
    float4 bv  = reinterpret_cast<const float4*>(bias)[tid];

    int jb = g_rowptr[node], je = g_rowptr[node + 1];

    float m = -1e30f, s = 0.f;
    float4 acc = make_float4(0.f, 0.f, 0.f, 0.f);
    const float4* xlp = reinterpret_cast<const float4*>(xl);

    int j = jb;
    for (; j + 4 <= je; j += 4) {
        int s0 = g_col[j], s1 = g_col[j + 1], s2 = g_col[j + 2], s3 = g_col[j + 3];
        float4 c0 = xlp[(size_t)s0 * 128 + tid];
        float4 c1 = xlp[(size_t)s1 * 128 + tid];
        float4 c2 = xlp[(size_t)s2 * 128 + tid];
        float4 c3 = xlp[(size_t)s3 * 128 + tid];
        float e0 = dot_lrelu(c0, xrv, av);
        float e1 = dot_lrelu(c1, xrv, av);
        float e2 = dot_lrelu(c2, xrv, av);
        float e3 = dot_lrelu(c3, xrv, av);
        e0 += __shfl_xor_sync(0xffffffffu, e0, 1, 16);
        e1 += __shfl_xor_sync(0xffffffffu, e1, 1, 16);
        e2 += __shfl_xor_sync(0xffffffffu, e2, 1, 16);
        e3 += __shfl_xor_sync(0xffffffffu, e3, 1, 16);
        e0 += __shfl_xor_sync(0xffffffffu, e0, 2, 16);
        e1 += __shfl_xor_sync(0xffffffffu, e1, 2, 16);
        e2 += __shfl_xor_sync(0xffffffffu, e2, 2, 16);
        e3 += __shfl_xor_sync(0xffffffffu, e3, 2, 16);
        e0 += __shfl_xor_sync(0xffffffffu, e0, 4, 16);
        e1 += __shfl_xor_sync(0xffffffffu, e1, 4, 16);
        e2 += __shfl_xor_sync(0xffffffffu, e2, 4, 16);
        e3 += __shfl_xor_sync(0xffffffffu, e3, 4, 16);
        e0 += __shfl_xor_sync(0xffffffffu, e0, 8, 16);
        e1 += __shfl_xor_sync(0xffffffffu, e1, 8, 16);
        e2 += __shfl_xor_sync(0xffffffffu, e2, 8, 16);
        e3 += __shfl_xor_sync(0xffffffffu, e3, 8, 16);

        float nm = fmaxf(m, fmaxf(fmaxf(e0, e1), fmaxf(e2, e3)));
        float sc = __expf(m - nm);
        float w0 = __expf(e0 - nm);
        float w1 = __expf(e1 - nm);
        float w2 = __expf(e2 - nm);
        float w3 = __expf(e3 - nm);
        s = s * sc + ((w0 + w1) + (w2 + w3));
        acc.x = acc.x * sc + ((w0 * c0.x + w1 * c1.x) + (w2 * c2.x + w3 * c3.x));
        acc.y = acc.y * sc + ((w0 * c0.y + w1 * c1.y) + (w2 * c2.y + w3 * c3.y));
        acc.z = acc.z * sc + ((w0 * c0.z + w1 * c1.z) + (w2 * c2.z + w3 * c3.z));
        acc.w = acc.w * sc + ((w0 * c0.w + w1 * c1.w) + (w2 * c2.w + w3 * c3.w));
        m = nm;
    }
    for (; j < je; j++) {
        int s0 = g_col[j];
        float4 c0 = xlp[(size_t)s0 * 128 + tid];
        float e0 = dot_lrelu(c0, xrv, av);
        e0 += __shfl_xor_sync(0xffffffffu, e0, 1, 16);
        e0 += __shfl_xor_sync(0xffffffffu, e0, 2, 16);
        e0 += __shfl_xor_sync(0xffffffffu, e0, 4, 16);
        e0 += __shfl_xor_sync(0xffffffffu, e0, 8, 16);
        float nm = fmaxf(m, e0);
        float sc = __expf(m - nm);
        float w0 = __expf(e0 - nm);
        s = s * sc + w0;
        acc.x = acc.x * sc + w0 * c0.x;
        acc.y = acc.y * sc + w0 * c0.y;
        acc.z = acc.z * sc + w0 * c0.z;
        acc.w = acc.w * sc + w0 * c0.w;
        m = nm;
    }

    float inv = 1.f / s;
    float4 o;
    o.x = fmaxf(acc.x * inv + bv.x, 0.f);
    o.y = fmaxf(acc.y * inv + bv.y, 0.f);
    o.z = fmaxf(acc.z * inv + bv.z, 0.f);
    o.w = fmaxf(acc.w * inv + bv.w, 0.f);
    reinterpret_cast<float4*>(hout + (size_t)node * HD)[tid] = o;
}

/* ----------------- layer-2 linear: warp = 2 nodes, L1-friendly W ---------- */
__global__ void __launch_bounds__(256)
k_lin2(const float* __restrict__ h,
       const float* __restrict__ bl, const float* __restrict__ br_,
       float* __restrict__ xl2, float* __restrict__ xr2)
{
    __shared__ __align__(16) float hsm[16][HD];
    int tid = threadIdx.x;
    int nb = blockIdx.x * 16;

    const float4* hp = reinterpret_cast<const float4*>(h + (size_t)nb * HD);
    float4* sp = reinterpret_cast<float4*>(hsm);
    #pragma unroll
    for (int i = 0; i < 8; i++) sp[tid + i * 256] = hp[tid + i * 256];
    __syncthreads();

    int wid = tid >> 5, lane = tid & 31;
    int nl = wid * 2 + (lane >> 4);
    int c  = lane & 15;                     /* cols 2c, 2c+1 */

    const unsigned long long* wp =
        reinterpret_cast<const unsigned long long*>(g_Wt2) + c;
    const float* hrow = hsm[nl];

    unsigned long long acc = 0ull;
    #pragma unroll 8
    for (int k = 0; k < HD; k++) {
        float hv = hrow[k];
        fma2(acc, pk2(hv, hv), wp[(size_t)k * 16]);
    }
    float2 r = upk2(acc);
    int node = nb + nl;
    int col = 2 * c;
    if (col < 16) {
        float2 o = make_float2(r.x + bl[col], r.y + bl[col + 1]);
        *reinterpret_cast<float2*>(xl2 + (size_t)node * NC + col) = o;
    } else {
        int cc = col - 16;
        float2 o = make_float2(r.x + br_[cc], r.y + br_[cc + 1]);
        *reinterpret_cast<float2*>(xr2 + (size_t)node * NC + cc) = o;
    }
}

/* --------------------- layer-2 GATv2, 4-edge unrolled --------------------- */
__global__ void __launch_bounds__(256)
k_gat2(const float* __restrict__ xl, const float* __restrict__ xr,
       const float* __restrict__ att, const float* __restrict__ bias,
       float* __restrict__ out)
{
    int node = blockIdx.x * 16 + (threadIdx.x >> 4);
    int lane = threadIdx.x & 15;
    if (node >= NN) return;

    float xrv = xr[(size_t)node * NC + lane];
    float av  = att[lane];

    int jb = g_rowptr[node], je = g_rowptr[node + 1];
    float m = -1e30f, s = 0.f, acc = 0.f;

    int j = jb;
    for (; j + 4 <= je; j += 4) {
        int s0 = g_col[j], s1 = g_col[j + 1], s2 = g_col[j + 2], s3 = g_col[j + 3];
        float c0 = xl[(size_t)s0 * NC + lane];
        float c1 = xl[(size_t)s1 * NC + lane];
        float c2 = xl[(size_t)s2 * NC + lane];
        float c3 = xl[(size_t)s3 * NC + lane];
        float e0 = lrelu(c0 + xrv) * av;
        float e1 = lrelu(c1 + xrv) * av;
        float e2 = lrelu(c2 + xrv) * av;
        float e3 = lrelu(c3 + xrv) * av;
        e0 += __shfl_xor_sync(0xffffffffu, e0, 1, 16);
        e1 += __shfl_xor_sync(0xffffffffu, e1, 1, 16);
        e2 += __shfl_xor_sync(0xffffffffu, e2, 1, 16);
        e3 += __shfl_xor_sync(0xffffffffu, e3, 1, 16);
        e0 += __shfl_xor_sync(0xffffffffu, e0, 2, 16);
        e1 += __shfl_xor_sync(0xffffffffu, e1, 2, 16);
        e2 += __shfl_xor_sync(0xffffffffu, e2, 2, 16);
        e3 += __shfl_xor_sync(0xffffffffu, e3, 2, 16);
        e0 += __shfl_xor_sync(0xffffffffu, e0, 4, 16);
        e1 += __shfl_xor_sync(0xffffffffu, e1, 4, 16);
        e2 += __shfl_xor_sync(0xffffffffu, e2, 4, 16);
        e3 += __shfl_xor_sync(0xffffffffu, e3, 4, 16);
        e0 += __shfl_xor_sync(0xffffffffu, e0, 8, 16);
        e1 += __shfl_xor_sync(0xffffffffu, e1, 8, 16);
        e2 += __shfl_xor_sync(0xffffffffu, e2, 8, 16);
        e3 += __shfl_xor_sync(0xffffffffu, e3, 8, 16);

        float nm = fmaxf(m, fmaxf(fmaxf(e0, e1), fmaxf(e2, e3)));
        float sc = __expf(m - nm);
        float w0 = __expf(e0 - nm);
        float w1 = __expf(e1 - nm);
        float w2 = __expf(e2 - nm);
        float w3 = __expf(e3 - nm);
        s = s * sc + ((w0 + w1) + (w2 + w3));
        acc = acc * sc + ((w0 * c0 + w1 * c1) + (w2 * c2 + w3 * c3));
        m = nm;
    }
    for (; j < je; j++) {
        int s0 = g_col[j];
        float c0 = xl[(size_t)s0 * NC + lane];
        float e0 = lrelu(c0 + xrv) * av;
        e0 += __shfl_xor_sync(0xffffffffu, e0, 1, 16);
        e0 += __shfl_xor_sync(0xffffffffu, e0, 2, 16);
        e0 += __shfl_xor_sync(0xffffffffu, e0, 4, 16);
        e0 += __shfl_xor_sync(0xffffffffu, e0, 8, 16);
        float nm = fmaxf(m, e0);
        float sc = __expf(m - nm);
        float w0 = __expf(e0 - nm);
        s = s * sc + w0;
        acc = acc * sc + w0 * c0;
        m = nm;
    }
    out[(size_t)node * NC + lane] = acc / s + bias[lane];
}

/* ------------------------------- launch ---------------------------------- */
extern "C" void kernel_launch(void* const* d_in, const int* in_sizes, int n_in,
                              void* d_out, int out_size)
{
    const float* x     = (const float*)d_in[0];
    const void*  ei    = d_in[1];
    const float* W_l1  = (const float*)d_in[2];
    const float* b_l1  = (const float*)d_in[3];
    const float* W_r1  = (const float*)d_in[4];
    const float* b_r1  = (const float*)d_in[5];
    const float* att1  = (const float*)d_in[6];
    const float* bias1 = (const float*)d_in[7];
    const float* W_l2  = (const float*)d_in[8];
    const float* b_l2  = (const float*)d_in[9];
    const float* W_r2  = (const float*)d_in[10];
    const float* b_r2  = (const float*)d_in[11];
    const float* att2  = (const float*)d_in[12];
    const float* bias2 = (const float*)d_in[13];
    float* out = (float*)d_out;

    float *xl1, *xr1, *h, *xl2, *xr2;
    cudaGetSymbolAddress((void**)&xl1, g_xl1);
    cudaGetSymbolAddress((void**)&xr1, g_xr1);
    cudaGetSymbolAddress((void**)&h,   g_h);
    cudaGetSymbolAddress((void**)&xl2, g_xl2);
    cudaGetSymbolAddress((void**)&xr2, g_xr2);

    cudaFuncSetAttribute(k_scan, cudaFuncAttributeMaxDynamicSharedMemorySize, NN * 4);
    cudaFuncSetAttribute(k_hmma, cudaFuncAttributeMaxDynamicSharedMemorySize, 6 * STG + 1024);

    int prep0_items = W_A + W_B + W_W;
    k_prep0<<<(prep0_items + 255) / 256, 256>>>(x, W_l1, W_r1, W_l2, W_r2);
    k_prep1<<<80, 256>>>((const int*)ei);
    k_hist<<<(ET + 255) / 256, 256>>>(ei);
    k_scan<<<1, 1024, NN * 4>>>();
    k_scatter<<<(ET + 255) / 256, 256>>>(ei);

    dim3 gm(NNP / 128, HD / 128, 2);
    k_hmma<<<gm, 256, 6 * STG + 1024>>>(b_l1, b_r1);   /* launch idx 5 → profiled */

    k_gat1<<<NN, 128>>>(xl1, xr1, att1, bias1, h);

    k_lin2<<<NN / 16, 256>>>(h, b_l2, b_r2, xl2, xr2);

    k_gat2<<<(NN + 15) / 16, 256>>>(xl2, xr2, att2, bias2, out);
}